// round 1
// baseline (speedup 1.0000x reference)
#include <cuda_runtime.h>
#include <cuda_bf16.h>
#include <cuda_fp16.h>
#include <cstdint>

// Problem constants
#define Dk   512
#define Ek   4
#define Vk   32000
#define Lk   1024
#define M2k  (Lk * Ek)     // 4096 rows for the big GEMM (token-major, expert inner)
#define N1k  (Ek * Dk)     // 2048 latent width

// ---------------------------------------------------------------------------
// Device scratch (allocation-free: static __device__ arrays)
// ---------------------------------------------------------------------------
__device__ __nv_bfloat16 g_Hbf[Lk * Dk];                 // hidden in bf16
__device__ __nv_bfloat16 g_Wlat[Dk * N1k];               // W_latent bf16
__device__ __nv_bfloat16 g_Wdec[Dk * Vk];                // W_dec bf16 [K][N]
__device__ __nv_bfloat16 g_latent[M2k * Dk];             // tanh latent bf16 [4096][512]
__device__ __half        g_logits[(size_t)M2k * Vk];     // 262 MB logits scratch (fp16)
__device__ float         g_logcoef[M2k];                 // log softmax of priors
__device__ float         g_sumexp[M2k];                  // per-(l,e) sum of exp(logit)
__device__ float         g_w[M2k];                       // exp(logcoef)/sumexp

// ---------------------------------------------------------------------------
// fp32 -> bf16 conversions (grid-stride)
// ---------------------------------------------------------------------------
__global__ void conv_kernel(const float* __restrict__ H,
                            const float* __restrict__ Wl,
                            const float* __restrict__ Wd) {
    int stride = gridDim.x * blockDim.x;
    int tid = blockIdx.x * blockDim.x + threadIdx.x;
    for (int j = tid; j < Lk * Dk; j += stride)  g_Hbf[j]  = __float2bfloat16(H[j]);
    for (int j = tid; j < Dk * N1k; j += stride) g_Wlat[j] = __float2bfloat16(Wl[j]);
    for (int j = tid; j < Dk * Vk; j += stride)  g_Wdec[j] = __float2bfloat16(Wd[j]);
}

// ---------------------------------------------------------------------------
// Prior: one warp per token computes 4 dot products + log_softmax over E.
// Also zeroes g_sumexp for this launch (deterministic per-call reset).
// ---------------------------------------------------------------------------
__global__ void prior_kernel(const float* __restrict__ H,
                             const float* __restrict__ Wp,
                             const float* __restrict__ bp) {
    int gtid = blockIdx.x * blockDim.x + threadIdx.x;
    if (gtid < M2k) g_sumexp[gtid] = 0.f;

    int w    = gtid >> 5;
    int lane = gtid & 31;
    if (w >= Lk) return;

    float a0 = 0.f, a1 = 0.f, a2 = 0.f, a3 = 0.f;
    const float* h = H + w * Dk;
    for (int d = lane; d < Dk; d += 32) {
        float hv = h[d];
        const float* wr = Wp + d * Ek;
        a0 += hv * wr[0]; a1 += hv * wr[1];
        a2 += hv * wr[2]; a3 += hv * wr[3];
    }
#pragma unroll
    for (int o = 16; o; o >>= 1) {
        a0 += __shfl_xor_sync(0xffffffffu, a0, o);
        a1 += __shfl_xor_sync(0xffffffffu, a1, o);
        a2 += __shfl_xor_sync(0xffffffffu, a2, o);
        a3 += __shfl_xor_sync(0xffffffffu, a3, o);
    }
    if (lane == 0) {
        float x0 = a0 + bp[0], x1 = a1 + bp[1], x2 = a2 + bp[2], x3 = a3 + bp[3];
        float mx = fmaxf(fmaxf(x0, x1), fmaxf(x2, x3));
        float s  = __expf(x0 - mx) + __expf(x1 - mx) + __expf(x2 - mx) + __expf(x3 - mx);
        float lse = mx + __logf(s);
        g_logcoef[w * Ek + 0] = x0 - lse;
        g_logcoef[w * Ek + 1] = x1 - lse;
        g_logcoef[w * Ek + 2] = x2 - lse;
        g_logcoef[w * Ek + 3] = x3 - lse;
    }
}

// ---------------------------------------------------------------------------
// bf16 GEMM: C[M,N] = A[M,512] * B[512,N], fp32 accum via mma.sync m16n8k16.
// 128x128x32 CTA tile, 8 warps (2x4), double-buffered cp.async pipeline.
// EPI==1: latent path (tanh + bias -> g_latent bf16)
// EPI==2: decoder path (bias -> g_logits fp16, plus per-row sum of exp)
// ---------------------------------------------------------------------------
#define BM 128
#define BN 128
#define BK 32
#define KT (Dk / BK)   // 16
#define PADA 40        // 32 + 8 bf16 pad -> 80B rows, conflict-free ldmatrix
#define PADB 136       // 128 + 8 bf16 pad -> 272B rows, conflict-free ldmatrix

template <int EPI>
__global__ __launch_bounds__(256, 2) void gemm_kernel(const float* __restrict__ bias) {
    constexpr int N = (EPI == 1) ? N1k : Vk;
    const __nv_bfloat16* __restrict__ A  = (EPI == 1) ? g_Hbf  : g_latent;
    const __nv_bfloat16* __restrict__ Bm = (EPI == 1) ? g_Wlat : g_Wdec;

    __shared__ __align__(16) __nv_bfloat16 As[2][BM][PADA];
    __shared__ __align__(16) __nv_bfloat16 Bs[2][BK][PADB];
    __shared__ float srow[BM];

    const int tid    = threadIdx.x;
    const int lane   = tid & 31;
    const int wid    = tid >> 5;
    const int warp_m = wid >> 2;   // 0..1
    const int warp_n = wid & 3;    // 0..3
    const int mBase  = blockIdx.y * BM;
    const int nBase  = blockIdx.x * BN;

    float c[4][4][4];
#pragma unroll
    for (int i = 0; i < 4; i++)
#pragma unroll
        for (int j = 0; j < 4; j++)
#pragma unroll
            for (int r = 0; r < 4; r++) c[i][j][r] = 0.f;

    auto issue = [&](int kt, int buf) {
#pragma unroll
        for (int s = 0; s < 2; s++) {          // A tile: 128 rows x 32 cols = 512 x16B
            int chunk = tid + s * 256;
            int arow = chunk >> 2, ac4 = chunk & 3;
            const __nv_bfloat16* gp = A + (size_t)(mBase + arow) * Dk + kt * BK + ac4 * 8;
            uint32_t sp = (uint32_t)__cvta_generic_to_shared(&As[buf][arow][ac4 * 8]);
            asm volatile("cp.async.cg.shared.global [%0], [%1], 16;\n" :: "r"(sp), "l"(gp));
        }
#pragma unroll
        for (int s = 0; s < 2; s++) {          // B tile: 32 rows x 128 cols = 512 x16B
            int chunk = tid + s * 256;
            int brow = chunk >> 4, bc4 = chunk & 15;
            const __nv_bfloat16* gp = Bm + (size_t)(kt * BK + brow) * N + nBase + bc4 * 8;
            uint32_t sp = (uint32_t)__cvta_generic_to_shared(&Bs[buf][brow][bc4 * 8]);
            asm volatile("cp.async.cg.shared.global [%0], [%1], 16;\n" :: "r"(sp), "l"(gp));
        }
    };

    auto compute = [&](int buf) {
#pragma unroll
        for (int ks = 0; ks < 2; ks++) {       // two k=16 steps per BK=32
            const int k0 = ks * 16;
            uint32_t a[4][4], b[4][2];
#pragma unroll
            for (int i = 0; i < 4; i++) {      // A frags: 4x (16x16)
                int row = warp_m * 64 + i * 16 + (lane & 7) + ((lane >> 3) & 1) * 8;
                int col = k0 + (lane >> 4) * 8;
                uint32_t ad = (uint32_t)__cvta_generic_to_shared(&As[buf][row][col]);
                asm volatile("ldmatrix.sync.aligned.m8n8.x4.shared.b16 {%0,%1,%2,%3}, [%4];"
                             : "=r"(a[i][0]), "=r"(a[i][1]), "=r"(a[i][2]), "=r"(a[i][3])
                             : "r"(ad));
            }
#pragma unroll
            for (int jj = 0; jj < 2; jj++) {   // B frags: 2x ldmatrix.x4.trans -> 4x (16x8)
                int krow = k0 + (lane & 7) + ((lane >> 3) & 1) * 8;
                int ncol = warp_n * 32 + jj * 16 + (lane >> 4) * 8;
                uint32_t ad = (uint32_t)__cvta_generic_to_shared(&Bs[buf][krow][ncol]);
                asm volatile("ldmatrix.sync.aligned.m8n8.x4.trans.shared.b16 {%0,%1,%2,%3}, [%4];"
                             : "=r"(b[jj * 2][0]), "=r"(b[jj * 2][1]),
                               "=r"(b[jj * 2 + 1][0]), "=r"(b[jj * 2 + 1][1])
                             : "r"(ad));
            }
#pragma unroll
            for (int i = 0; i < 4; i++)
#pragma unroll
                for (int j = 0; j < 4; j++) {
                    asm volatile(
                        "mma.sync.aligned.m16n8k16.row.col.f32.bf16.bf16.f32 "
                        "{%0,%1,%2,%3}, {%4,%5,%6,%7}, {%8,%9}, {%0,%1,%2,%3};"
                        : "+f"(c[i][j][0]), "+f"(c[i][j][1]), "+f"(c[i][j][2]), "+f"(c[i][j][3])
                        : "r"(a[i][0]), "r"(a[i][1]), "r"(a[i][2]), "r"(a[i][3]),
                          "r"(b[j][0]), "r"(b[j][1]));
                }
        }
    };

    issue(0, 0);
    asm volatile("cp.async.commit_group;\n");
    issue(1, 1);
    asm volatile("cp.async.commit_group;\n");

    for (int kt = 0; kt < KT; kt++) {
        if (kt < KT - 1) { asm volatile("cp.async.wait_group 1;\n"); }
        else             { asm volatile("cp.async.wait_group 0;\n"); }
        __syncthreads();
        compute(kt & 1);
        if (kt + 2 < KT) {
            __syncthreads();                    // all warps done with buf before overwrite
            issue(kt + 2, kt & 1);
            asm volatile("cp.async.commit_group;\n");
        }
    }

    // ---------------- epilogue ----------------
    if (EPI == 1) {
#pragma unroll
        for (int j = 0; j < 4; j++) {
            int col = nBase + warp_n * 32 + j * 8 + (lane & 3) * 2;
            float b0 = bias[col], b1 = bias[col + 1];
#pragma unroll
            for (int i = 0; i < 4; i++) {
                int row = mBase + warp_m * 64 + i * 16 + (lane >> 2);
                __nv_bfloat162 p0 = __floats2bfloat162_rn(tanhf(c[i][j][0] + b0),
                                                          tanhf(c[i][j][1] + b1));
                __nv_bfloat162 p1 = __floats2bfloat162_rn(tanhf(c[i][j][2] + b0),
                                                          tanhf(c[i][j][3] + b1));
                *reinterpret_cast<__nv_bfloat162*>(&g_latent[(size_t)row * N + col]) = p0;
                *reinterpret_cast<__nv_bfloat162*>(&g_latent[(size_t)(row + 8) * N + col]) = p1;
            }
        }
    } else {
        if (tid < BM) srow[tid] = 0.f;
        __syncthreads();
        float rs[4][2];
#pragma unroll
        for (int i = 0; i < 4; i++) { rs[i][0] = 0.f; rs[i][1] = 0.f; }
#pragma unroll
        for (int j = 0; j < 4; j++) {
            int col = nBase + warp_n * 32 + j * 8 + (lane & 3) * 2;
            float b0 = bias[col], b1 = bias[col + 1];
#pragma unroll
            for (int i = 0; i < 4; i++) {
                int row = mBase + warp_m * 64 + i * 16 + (lane >> 2);
                float v00 = c[i][j][0] + b0, v01 = c[i][j][1] + b1;   // row
                float v10 = c[i][j][2] + b0, v11 = c[i][j][3] + b1;   // row+8
                *reinterpret_cast<__half2*>(&g_logits[(size_t)row * Vk + col]) =
                    __floats2half2_rn(v00, v01);
                *reinterpret_cast<__half2*>(&g_logits[(size_t)(row + 8) * Vk + col]) =
                    __floats2half2_rn(v10, v11);
                rs[i][0] += __expf(v00) + __expf(v01);
                rs[i][1] += __expf(v10) + __expf(v11);
            }
        }
#pragma unroll
        for (int i = 0; i < 4; i++)
#pragma unroll
            for (int h = 0; h < 2; h++) {
                float v = rs[i][h];
                v += __shfl_xor_sync(0xffffffffu, v, 1);
                v += __shfl_xor_sync(0xffffffffu, v, 2);
                if ((lane & 3) == 0)
                    atomicAdd(&srow[warp_m * 64 + i * 16 + (lane >> 2) + h * 8], v);
            }
        __syncthreads();
        if (tid < BM) atomicAdd(&g_sumexp[mBase + tid], srow[tid]);
    }
}

// ---------------------------------------------------------------------------
// w[l,e] = exp(log_coef) / sumexp  (mixture weight over normalized softmax)
// ---------------------------------------------------------------------------
__global__ void prep_w_kernel() {
    int m = blockIdx.x * blockDim.x + threadIdx.x;
    if (m < M2k) g_w[m] = __expf(g_logcoef[m]) / g_sumexp[m];
}

// ---------------------------------------------------------------------------
// out[l,v] = log( sum_e w[l,e] * exp(logit[l,e,v]) )
// ---------------------------------------------------------------------------
__global__ void combine_kernel(float* __restrict__ out) {
    int v = blockIdx.x * blockDim.x + threadIdx.x;   // 125*256 == 32000 exactly
    int l = blockIdx.y;
    const __half* lp = g_logits + (size_t)l * Ek * Vk + v;
    const float*  wp = g_w + l * Ek;
    float s = 0.f;
#pragma unroll
    for (int e = 0; e < Ek; e++)
        s += wp[e] * __expf(__half2float(lp[(size_t)e * Vk]));
    out[(size_t)l * Vk + v] = __logf(s);
}

// ---------------------------------------------------------------------------
// Entry point (graph-capturable: kernel launches only, default stream)
// ---------------------------------------------------------------------------
extern "C" void kernel_launch(void* const* d_in, const int* in_sizes, int n_in,
                              void* d_out, int out_size) {
    const float* H  = (const float*)d_in[0];   // hidden_states [1,1024,512]
    const float* Wp = (const float*)d_in[1];   // W_prior [512,4]
    const float* bp = (const float*)d_in[2];   // b_prior [4]
    const float* Wl = (const float*)d_in[3];   // W_latent [512,2048]
    const float* bl = (const float*)d_in[4];   // b_latent [2048]
    const float* Wd = (const float*)d_in[5];   // W_dec [512,32000]
    const float* bd = (const float*)d_in[6];   // b_dec [32000]
    float* out = (float*)d_out;                // [1,1024,32000]

    conv_kernel<<<2048, 256>>>(H, Wl, Wd);
    prior_kernel<<<128, 256>>>(H, Wp, bp);
    gemm_kernel<1><<<dim3(N1k / BN, Lk / BM), 256>>>(bl);     // (16, 8)
    gemm_kernel<2><<<dim3(Vk / BN, M2k / BM), 256>>>(bd);     // (250, 32)
    prep_w_kernel<<<(M2k + 255) / 256, 256>>>();
    combine_kernel<<<dim3(Vk / 256, Lk), 256>>>(out);         // (125, 1024)
}